// round 2
// baseline (speedup 1.0000x reference)
#include <cuda_runtime.h>

// Scalar DCP reduction, single-kernel with last-block finalize:
// result = sum_{b,r,c} w(r)*w(c)*|min over 3 channels of x[b,ch,r,c]|
// with w = 2 at index 0 or 1023, else 3. (Zero padding contributes 0.)

#define B    16
#define H    1024
#define Wd   1024
#define W4   256                // Wd / 4
#define CH   (1024LL*1024LL)    // channel stride in floats
#define GRID 2048
#define TPB  256
#define ITER 8                  // GRID*TPB*ITER == B*H*W4 == 4,194,304

__device__ float        g_part[GRID];
__device__ unsigned int g_ticket;   // zero-initialized; self-resets via wrap

__global__ __launch_bounds__(TPB) void dcp_kernel(const float* __restrict__ x,
                                                  float* __restrict__ out) {
    const long long stride = (long long)GRID * TPB;
    long long i0 = (long long)blockIdx.x * TPB + threadIdx.x;

    float tsum = 0.f;

    #pragma unroll
    for (int it = 0; it < ITER; it++) {
        long long i = i0 + (long long)it * stride;
        int c4 = (int)(i & (W4 - 1));
        long long t = i >> 8;          // / W4
        int r = (int)(t & (H - 1));
        long long b = t >> 10;         // / H

        const float4* base = (const float4*)(x + b * 3 * CH
                                             + (long long)r * Wd) + c4;
        float4 a0 = __ldcs(base);
        float4 a1 = __ldcs(base + (CH >> 2));
        float4 a2 = __ldcs(base + (CH >> 1));

        float m0 = fabsf(fminf(fminf(a0.x, a1.x), a2.x));
        float m1 = fabsf(fminf(fminf(a0.y, a1.y), a2.y));
        float m2 = fabsf(fminf(fminf(a0.z, a1.z), a2.z));
        float m3 = fabsf(fminf(fminf(a0.w, a1.w), a2.w));

        float wr = (r == 0 || r == H - 1) ? 2.f : 3.f;
        int c0 = c4 * 4;
        float w0 = (c0 == 0) ? 2.f : 3.f;            // first col of row
        float w3 = (c0 + 3 == Wd - 1) ? 2.f : 3.f;   // last col of row

        tsum += wr * (w0 * m0 + 3.f * m1 + 3.f * m2 + w3 * m3);
    }

    // intra-block reduction
    #pragma unroll
    for (int ofs = 16; ofs > 0; ofs >>= 1)
        tsum += __shfl_xor_sync(0xFFFFFFFFu, tsum, ofs);

    __shared__ float warp_sums[TPB / 32];
    int lane = threadIdx.x & 31;
    int wid  = threadIdx.x >> 5;
    if (lane == 0) warp_sums[wid] = tsum;
    __syncthreads();

    __shared__ bool is_last;
    if (threadIdx.x == 0) {
        float v = 0.f;
        #pragma unroll
        for (int w = 0; w < TPB / 32; w++) v += warp_sums[w];
        g_part[blockIdx.x] = v;
        __threadfence();
        // wraps to 0 when old == GRID-1 -> state auto-resets every run
        unsigned int old = atomicInc(&g_ticket, GRID - 1);
        is_last = (old == GRID - 1);
    }
    __syncthreads();

    if (is_last) {
        // last block: reduce all partials in double for accuracy
        double d = 0.0;
        for (int j = threadIdx.x; j < GRID; j += TPB)
            d += (double)g_part[j];
        // warp+block reduce in double via shared
        __shared__ double dsum[TPB / 32];
        #pragma unroll
        for (int ofs = 16; ofs > 0; ofs >>= 1)
            d += __shfl_xor_sync(0xFFFFFFFFu, d, ofs);
        if (lane == 0) dsum[wid] = d;
        __syncthreads();
        if (threadIdx.x == 0) {
            double tot = 0.0;
            #pragma unroll
            for (int w = 0; w < TPB / 32; w++) tot += dsum[w];
            out[0] = (float)tot;
        }
    }
}

extern "C" void kernel_launch(void* const* d_in, const int* in_sizes, int n_in,
                              void* d_out, int out_size) {
    const float* x = (const float*)d_in[0];
    dcp_kernel<<<GRID, TPB>>>(x, (float*)d_out);
}

// round 3
// speedup vs baseline: 1.0272x; 1.0272x over previous
#include <cuda_runtime.h>

// Scalar DCP reduction, single kernel, last-block finalize.
// result = sum_{b,r,c} w(r)*w(c)*|min over 3 channels of x[b,ch,r,c]|
// w = 2 at index 0 or 1023, else 3. Zero padding contributes 0.
//
// All indexing 32-bit: N4 = 16*1024*256 = 4,194,304 vec4 positions,
// channel stride = 1024*1024 floats = 2^18 float4.

#define TPB   256
#define GRID  1184              // 148 SMs * 8 blocks -> one full wave
#define N4    4194304u
#define CH4   262144u           // 2^18 float4 per channel

__device__ float        g_part[GRID];
__device__ unsigned int g_ticket;   // zero-init; wraps back to 0 each run

__global__ __launch_bounds__(TPB) void dcp_kernel(const float* __restrict__ x,
                                                  float* __restrict__ out) {
    const unsigned stride = GRID * TPB;
    float tsum = 0.f;

    #pragma unroll 2
    for (unsigned i = blockIdx.x * TPB + threadIdx.x; i < N4; i += stride) {
        unsigned c4 = i & 255u;
        unsigned r  = (i >> 8) & 1023u;
        unsigned b  = i >> 18;

        const float4* p = (const float4*)x + (b * 3u << 18) + (r << 8) + c4;
        float4 a0 = p[0];
        float4 a1 = p[CH4];
        float4 a2 = p[2u * CH4];

        float m0 = fabsf(fminf(fminf(a0.x, a1.x), a2.x));
        float m1 = fabsf(fminf(fminf(a0.y, a1.y), a2.y));
        float m2 = fabsf(fminf(fminf(a0.z, a1.z), a2.z));
        float m3 = fabsf(fminf(fminf(a0.w, a1.w), a2.w));

        float wr = (r == 0u || r == 1023u) ? 2.f : 3.f;
        float w0 = (c4 == 0u)   ? 2.f : 3.f;   // col 0 lives in first vec
        float w3 = (c4 == 255u) ? 2.f : 3.f;   // col 1023 in last vec

        float s = fmaf(w0, m0, fmaf(3.f, m1 + m2, w3 * m3));
        tsum = fmaf(wr, s, tsum);
    }

    // intra-block reduction
    #pragma unroll
    for (int ofs = 16; ofs > 0; ofs >>= 1)
        tsum += __shfl_xor_sync(0xFFFFFFFFu, tsum, ofs);

    __shared__ float warp_sums[TPB / 32];
    int lane = threadIdx.x & 31;
    int wid  = threadIdx.x >> 5;
    if (lane == 0) warp_sums[wid] = tsum;
    __syncthreads();

    __shared__ bool is_last;
    if (threadIdx.x == 0) {
        float v = 0.f;
        #pragma unroll
        for (int w = 0; w < TPB / 32; w++) v += warp_sums[w];
        g_part[blockIdx.x] = v;
        __threadfence();
        unsigned old = atomicInc(&g_ticket, GRID - 1);  // self-resets
        is_last = (old == GRID - 1);
    }
    __syncthreads();

    if (is_last) {
        double d = 0.0;
        for (int j = threadIdx.x; j < GRID; j += TPB)
            d += (double)g_part[j];
        #pragma unroll
        for (int ofs = 16; ofs > 0; ofs >>= 1)
            d += __shfl_xor_sync(0xFFFFFFFFu, d, ofs);
        __shared__ double dsum[TPB / 32];
        if (lane == 0) dsum[wid] = d;
        __syncthreads();
        if (threadIdx.x == 0) {
            double tot = 0.0;
            #pragma unroll
            for (int w = 0; w < TPB / 32; w++) tot += dsum[w];
            out[0] = (float)tot;
        }
    }
}

extern "C" void kernel_launch(void* const* d_in, const int* in_sizes, int n_in,
                              void* d_out, int out_size) {
    const float* x = (const float*)d_in[0];
    dcp_kernel<<<GRID, TPB>>>(x, (float*)d_out);
}

// round 4
// speedup vs baseline: 1.0468x; 1.0191x over previous
#include <cuda_runtime.h>

// Scalar DCP reduction, single kernel, last-block finalize.
// result = sum_{b,r,c} w(r)*w(c)*|min over 3 channels of x[b,ch,r,c]|
// w = 2 at index 0 or 1023, else 3. Zero padding contributes 0.
//
// 32-bit indexing throughout. Forced 8 blocks/SM (<=32 regs) for 100%
// theoretical occupancy: the kernel is DRAM-latency-hiding-bound and needs
// resident warps, not ILP.

#define TPB   256
#define GRID  1184              // 148 SMs * 8 blocks -> exactly one wave
#define N4    4194304u          // 16*1024*256 vec4 positions
#define CH4   262144u           // 2^18 float4 per channel

__device__ float        g_part[GRID];
__device__ unsigned int g_ticket;   // zero-init; wraps back to 0 each run

__global__ __launch_bounds__(TPB, 8) void dcp_kernel(const float* __restrict__ x,
                                                     float* __restrict__ out) {
    const unsigned stride = GRID * TPB;
    float tsum = 0.f;

    #pragma unroll 1
    for (unsigned i = blockIdx.x * TPB + threadIdx.x; i < N4; i += stride) {
        unsigned c4 = i & 255u;
        unsigned r  = (i >> 8) & 1023u;
        unsigned b  = i >> 18;

        const float4* p = (const float4*)x + (b * 3u << 18) + (r << 8) + c4;
        float4 a0 = p[0];
        float4 a1 = p[CH4];
        float4 a2 = p[2u * CH4];

        float m0 = fabsf(fminf(fminf(a0.x, a1.x), a2.x));
        float m1 = fabsf(fminf(fminf(a0.y, a1.y), a2.y));
        float m2 = fabsf(fminf(fminf(a0.z, a1.z), a2.z));
        float m3 = fabsf(fminf(fminf(a0.w, a1.w), a2.w));

        float wr = (r == 0u || r == 1023u) ? 2.f : 3.f;
        float w0 = (c4 == 0u)   ? 2.f : 3.f;   // col 0 lives in first vec
        float w3 = (c4 == 255u) ? 2.f : 3.f;   // col 1023 in last vec

        float s = fmaf(w0, m0, fmaf(3.f, m1 + m2, w3 * m3));
        tsum = fmaf(wr, s, tsum);
    }

    // intra-block reduction
    #pragma unroll
    for (int ofs = 16; ofs > 0; ofs >>= 1)
        tsum += __shfl_xor_sync(0xFFFFFFFFu, tsum, ofs);

    __shared__ float warp_sums[TPB / 32];
    int lane = threadIdx.x & 31;
    int wid  = threadIdx.x >> 5;
    if (lane == 0) warp_sums[wid] = tsum;
    __syncthreads();

    __shared__ bool is_last;
    if (threadIdx.x == 0) {
        float v = 0.f;
        #pragma unroll
        for (int w = 0; w < TPB / 32; w++) v += warp_sums[w];
        g_part[blockIdx.x] = v;
        __threadfence();
        unsigned old = atomicInc(&g_ticket, GRID - 1);  // self-resets
        is_last = (old == GRID - 1);
    }
    __syncthreads();

    if (is_last) {
        double d = 0.0;
        for (int j = threadIdx.x; j < GRID; j += TPB)
            d += (double)g_part[j];
        #pragma unroll
        for (int ofs = 16; ofs > 0; ofs >>= 1)
            d += __shfl_xor_sync(0xFFFFFFFFu, d, ofs);
        __shared__ double dsum[TPB / 32];
        if (lane == 0) dsum[wid] = d;
        __syncthreads();
        if (threadIdx.x == 0) {
            double tot = 0.0;
            #pragma unroll
            for (int w = 0; w < TPB / 32; w++) tot += dsum[w];
            out[0] = (float)tot;
        }
    }
}

extern "C" void kernel_launch(void* const* d_in, const int* in_sizes, int n_in,
                              void* d_out, int out_size) {
    const float* x = (const float*)d_in[0];
    dcp_kernel<<<GRID, TPB>>>(x, (float*)d_out);
}